// round 2
// baseline (speedup 1.0000x reference)
#include <cuda_runtime.h>

// ---------------------------------------------------------------------------
// Problem constants
//   volumes: 3 × [128 complex channels][256][256]
//   points : 131072, output [131072][16] float32
// ---------------------------------------------------------------------------
#define NPTS_K 131072

// Scratch (static __device__, allocation-free per harness rules)
__device__ float g_alpha;
__device__ float g_twre[256];              // E[j] = exp(+2*pi*i*j/256)
__device__ float g_twim[256];
__device__ float g_tmp_re[8388608];        // 32 MB plane (pass-1 output, reused per volume)
__device__ float g_tmp_im[8388608];        // 32 MB
// Final sample volumes, interleaved complex: [H=256][W=256][C=128][re,im]
__device__ float g_vol[3][16777216];       // 3 × 64 MB

__device__ __forceinline__ int brev8(int k) { return (int)(__brev((unsigned)k) >> 24); }

// ---------------------------------------------------------------------------
// init: alpha = softplus_b10(alpha_params)[0]; twiddle table
// ---------------------------------------------------------------------------
__global__ void init_kernel(const float* __restrict__ alpha_params) {
    int t = threadIdx.x;
    if (t < 256) {
        float s, c;
        sincospif((float)t * (1.0f / 128.0f), &s, &c);   // 2*pi*t/256 = pi*(t/128)
        g_twre[t] = c;
        g_twim[t] = s;
    }
    if (t == 0) {
        float a  = alpha_params[0];
        float bx = 10.0f * a;
        g_alpha = (bx > 1.0f) ? a : 0.1f * log1pf(expf(fminf(bx, 30.0f)));
    }
}

// ---------------------------------------------------------------------------
// Shared radix-2 DIT stage loop: 8 rows of 256 complex in smem (row-major),
// input already bit-reversed within each row. Inverse transform (sign +),
// unnormalized. 512 threads -> 2 butterflies/thread/stage.
// ---------------------------------------------------------------------------
__device__ __forceinline__ void fft8_rows(float* sre, float* sim,
                                          const float* twr, const float* twi, int tid) {
#pragma unroll
    for (int len = 2; len <= 256; len <<= 1) {
        int half = len >> 1;
        int tws  = 256 / len;
#pragma unroll
        for (int s = 0; s < 2; s++) {
            int bi  = tid + (s << 9);
            int row = bi >> 7;
            int j   = bi & 127;
            int grp = j / half;
            int pos = j - grp * half;
            int i1  = (row << 8) + grp * len + pos;
            int i2  = i1 + half;
            float wr = twr[pos * tws], wi = twi[pos * tws];
            float br = sre[i2], bm = sim[i2];
            float tr = br * wr - bm * wi;
            float ti = br * wi + bm * wr;
            float ar = sre[i1], ai = sim[i1];
            sre[i1] = ar + tr;  sim[i1] = ai + ti;
            sre[i2] = ar - tr;  sim[i2] = ai - ti;
        }
        __syncthreads();
    }
}

// ---------------------------------------------------------------------------
// Pass 1 (contiguous axis), flat view [32768 lines][256]. Used for Fx and Fy.
// Applies alpha. Output -> g_tmp, same flat layout. Fully coalesced.
// ---------------------------------------------------------------------------
__global__ __launch_bounds__(512) void fft_pass1_flat(const float* __restrict__ in_re,
                                                      const float* __restrict__ in_im) {
    __shared__ float sre[2048], sim[2048];
    __shared__ float twr[256], twi[256];
    int tid = threadIdx.x;
    if (tid < 256) { twr[tid] = g_twre[tid]; twi[tid] = g_twim[tid]; }
    float alpha = g_alpha;
    int base = blockIdx.x << 11;                   // 8 lines * 256
#pragma unroll
    for (int s = 0; s < 4; s++) {
        int idx = tid + (s << 9);
        int row = idx >> 8, k = idx & 255;
        int dst = (row << 8) | brev8(k);
        sre[dst] = in_re[base + idx] * alpha;
        sim[dst] = in_im[base + idx] * alpha;
    }
    __syncthreads();
    fft8_rows(sre, sim, twr, twi, tid);
#pragma unroll
    for (int s = 0; s < 4; s++) {
        int idx = tid + (s << 9);
        g_tmp_re[base + idx] = sre[idx];
        g_tmp_im[base + idx] = sim[idx];
    }
}

// ---------------------------------------------------------------------------
// Pass 1 for Fz: input [4096 (f,x)][256 y][8 d], transform along y.
// Block = one (f,x): load 8 KB contiguous, FFT 8 lines (one per d).
// ---------------------------------------------------------------------------
__global__ __launch_bounds__(512) void fft_pass1_z(const float* __restrict__ in_re,
                                                   const float* __restrict__ in_im) {
    __shared__ float sre[2048], sim[2048];         // smem layout [d][y]
    __shared__ float twr[256], twi[256];
    int tid = threadIdx.x;
    if (tid < 256) { twr[tid] = g_twre[tid]; twi[tid] = g_twim[tid]; }
    float alpha = g_alpha;
    int base = blockIdx.x << 11;
#pragma unroll
    for (int s = 0; s < 4; s++) {
        int idx = tid + (s << 9);
        int y = idx >> 3, d = idx & 7;
        int dst = (d << 8) | brev8(y);
        sre[dst] = in_re[base + idx] * alpha;
        sim[dst] = in_im[base + idx] * alpha;
    }
    __syncthreads();
    fft8_rows(sre, sim, twr, twi, tid);
#pragma unroll
    for (int s = 0; s < 4; s++) {
        int idx = tid + (s << 9);
        int y = idx >> 3, d = idx & 7;
        g_tmp_re[base + idx] = sre[(d << 8) + y];
        g_tmp_im[base + idx] = sim[(d << 8) + y];
    }
}

// ---------------------------------------------------------------------------
// Pass 2 (strided axis) + layout transform into gather volumes.
// g_tmp viewed as [O][256][I], FFT along the middle axis:
//   vid 0 (Fx): O=128 (c)    I=256  (z)      out: vol0[h=n][w=i][c=o]
//   vid 1 (Fy): O=16  (f)    I=2048 (d,z)    out: vol1[h=n(x)][w=z][c=8o+d]
//   vid 2 (Fz): O=16  (f)    I=2048 (y,d)    out: vol2[h=y][w=n(x)][c=8o+d]
// Block = (o, 16-wide I tile): 16 lines in smem (stride 17 to dodge bank
// conflicts), coalesced 64B loads. Final stores are scattered float2 (known
// 4x sector inflation -- optimization target for a later round).
// ---------------------------------------------------------------------------
__global__ __launch_bounds__(512) void fft_pass2(int I, int vid) {
    __shared__ float sre[256 * 17], sim[256 * 17];
    __shared__ float twr[256], twi[256];
    int tid = threadIdx.x;
    if (tid < 256) { twr[tid] = g_twre[tid]; twi[tid] = g_twim[tid]; }
    int o  = blockIdx.y;
    int i0 = blockIdx.x << 4;
    int obase = o * (256 * I) + i0;
#pragma unroll
    for (int s = 0; s < 8; s++) {
        int idx = tid + (s << 9);
        int k = idx >> 4, ii = idx & 15;
        int dst = brev8(k) * 17 + ii;
        int src = obase + k * I + ii;
        sre[dst] = g_tmp_re[src];
        sim[dst] = g_tmp_im[src];
    }
    __syncthreads();
#pragma unroll
    for (int len = 2; len <= 256; len <<= 1) {
        int half = len >> 1;
        int tws  = 256 / len;
#pragma unroll
        for (int s = 0; s < 4; s++) {
            int bi = tid + (s << 9);
            int ii = bi & 15;
            int j  = bi >> 4;
            int grp = j / half;
            int pos = j - grp * half;
            int i1  = (grp * len + pos) * 17 + ii;
            int i2  = i1 + half * 17;
            float wr = twr[pos * tws], wi = twi[pos * tws];
            float br = sre[i2], bm = sim[i2];
            float tr = br * wr - bm * wi;
            float ti = br * wi + bm * wr;
            float ar = sre[i1], ai = sim[i1];
            sre[i1] = ar + tr;  sim[i1] = ai + ti;
            sre[i2] = ar - tr;  sim[i2] = ai - ti;
        }
        __syncthreads();
    }
    float2* vol = reinterpret_cast<float2*>(g_vol[vid]);
#pragma unroll
    for (int s = 0; s < 8; s++) {
        int idx = tid + (s << 9);
        int k = idx >> 4, ii = idx & 15;
        int h, w, c;
        if (vid == 0)      { h = k;        w = i0 + ii;        c = o; }
        else if (vid == 1) { int i = i0 + ii; h = k;      w = i & 255; c = (o << 3) + (i >> 8); }
        else               { int i = i0 + ii; h = i >> 3; w = k;       c = (o << 3) + (i & 7); }
        vol[(((h << 8) + w) << 7) + c] = make_float2(sre[k * 17 + ii], sim[k * 17 + ii]);
    }
}

// ---------------------------------------------------------------------------
// Gather: one warp per point. Lane L owns channels c = 4L..4L+3 (f = L/2,
// d = 4*(L&1)+j). Each tap = 1 KB contiguous (2x float4 per lane).
// Twiddles: lanes 0..23 compute sincospif once (axis = lane/8, d = lane%8),
// distributed via shuffles. Pair-reduce (xor 1) -> 16 outputs per point.
// ---------------------------------------------------------------------------
__global__ __launch_bounds__(256) void gather_kernel(const float* __restrict__ pts,
                                                     float* __restrict__ out) {
    int warp = (blockIdx.x << 3) + (threadIdx.x >> 5);
    int lane = threadIdx.x & 31;

    const float px = pts[warp * 3 + 0];
    const float py = pts[warp * 3 + 1];
    const float pz = pts[warp * 3 + 2];

    // cooperative irfft twiddles
    float cval, sval;
    {
        int a = lane >> 3, d = lane & 7;
        float q  = (a == 0) ? px : ((a == 1) ? py : pz);
        float xx = (q + 1.0f) * (0.5f * 255.0f / 256.0f);
        float s_, c_;
        sincospif(2.0f * xx * (float)d, &s_, &c_);
        float sc = d ? 2.0f : 1.0f;
        cval = c_ * sc;
        sval = s_ * sc;
    }

    // per-coordinate bilinear params (align_corners=True, clipped)
    int q0[3], q1[3]; float wf[3];
    {
        float qv[3] = { px, py, pz };
#pragma unroll
        for (int a = 0; a < 3; a++) {
            float ii = (qv[a] + 1.0f) * 127.5f;
            float f0 = floorf(ii);
            wf[a] = ii - f0;
            int i0 = (int)f0;
            i0 = max(0, min(255, i0));
            q0[a] = i0;
            q1[a] = min(i0 + 1, 255);
        }
    }

    float acc = 0.0f;
    int dhalf = (lane & 1) << 2;
#pragma unroll
    for (int v = 0; v < 3; v++) {
        int h0, h1, w0, w1; float wy, wx;
        if (v == 0)      { h0 = q0[1]; h1 = q1[1]; wy = wf[1]; w0 = q0[2]; w1 = q1[2]; wx = wf[2]; }
        else if (v == 1) { h0 = q0[0]; h1 = q1[0]; wy = wf[0]; w0 = q0[2]; w1 = q1[2]; wx = wf[2]; }
        else             { h0 = q0[1]; h1 = q1[1]; wy = wf[1]; w0 = q0[0]; w1 = q1[0]; wx = wf[0]; }
        float w00 = (1.0f - wy) * (1.0f - wx);
        float w01 = (1.0f - wy) * wx;
        float w10 = wy * (1.0f - wx);
        float w11 = wy * wx;

        const float4* V = reinterpret_cast<const float4*>(g_vol[v]);
        int b00 = (((h0 << 8) + w0) << 6) + (lane << 1);
        int b01 = (((h0 << 8) + w1) << 6) + (lane << 1);
        int b10 = (((h1 << 8) + w0) << 6) + (lane << 1);
        int b11 = (((h1 << 8) + w1) << 6) + (lane << 1);

        float rr0 = 0, ri0 = 0, rr1 = 0, ri1 = 0, rr2 = 0, ri2 = 0, rr3 = 0, ri3 = 0;
        {
            float4 a = V[b00], b = V[b00 + 1];
            rr0 += w00 * a.x; ri0 += w00 * a.y; rr1 += w00 * a.z; ri1 += w00 * a.w;
            rr2 += w00 * b.x; ri2 += w00 * b.y; rr3 += w00 * b.z; ri3 += w00 * b.w;
        }
        {
            float4 a = V[b01], b = V[b01 + 1];
            rr0 += w01 * a.x; ri0 += w01 * a.y; rr1 += w01 * a.z; ri1 += w01 * a.w;
            rr2 += w01 * b.x; ri2 += w01 * b.y; rr3 += w01 * b.z; ri3 += w01 * b.w;
        }
        {
            float4 a = V[b10], b = V[b10 + 1];
            rr0 += w10 * a.x; ri0 += w10 * a.y; rr1 += w10 * a.z; ri1 += w10 * a.w;
            rr2 += w10 * b.x; ri2 += w10 * b.y; rr3 += w10 * b.z; ri3 += w10 * b.w;
        }
        {
            float4 a = V[b11], b = V[b11 + 1];
            rr0 += w11 * a.x; ri0 += w11 * a.y; rr1 += w11 * a.z; ri1 += w11 * a.w;
            rr2 += w11 * b.x; ri2 += w11 * b.y; rr3 += w11 * b.z; ri3 += w11 * b.w;
        }

        int sb = (v << 3) + dhalf;
        float tc0 = __shfl_sync(0xffffffffu, cval, sb + 0);
        float ts0 = __shfl_sync(0xffffffffu, sval, sb + 0);
        float tc1 = __shfl_sync(0xffffffffu, cval, sb + 1);
        float ts1 = __shfl_sync(0xffffffffu, sval, sb + 1);
        float tc2 = __shfl_sync(0xffffffffu, cval, sb + 2);
        float ts2 = __shfl_sync(0xffffffffu, sval, sb + 2);
        float tc3 = __shfl_sync(0xffffffffu, cval, sb + 3);
        float ts3 = __shfl_sync(0xffffffffu, sval, sb + 3);

        acc += rr0 * tc0 - ri0 * ts0;
        acc += rr1 * tc1 - ri1 * ts1;
        acc += rr2 * tc2 - ri2 * ts2;
        acc += rr3 * tc3 - ri3 * ts3;
    }

    acc += __shfl_xor_sync(0xffffffffu, acc, 1);
    if ((lane & 1) == 0) out[(warp << 4) + (lane >> 1)] = acc;
}

// ---------------------------------------------------------------------------
// Launch: all on the default stream (graph-capturable, allocation-free).
// tmp buffer is reused per volume; stream ordering provides the dependency.
// ---------------------------------------------------------------------------
extern "C" void kernel_launch(void* const* d_in, const int* in_sizes, int n_in,
                              void* d_out, int out_size) {
    const float* pts   = (const float*)d_in[0];
    const float* Fx_re = (const float*)d_in[1];
    const float* Fx_im = (const float*)d_in[2];
    const float* Fy_re = (const float*)d_in[3];
    const float* Fy_im = (const float*)d_in[4];
    const float* Fz_re = (const float*)d_in[5];
    const float* Fz_im = (const float*)d_in[6];
    const float* ap    = (const float*)d_in[7];
    float* out = (float*)d_out;

    init_kernel<<<1, 256>>>(ap);

    // Fx: [c=128][y=256][z=256]; pass1 along z, pass2 along y
    fft_pass1_flat<<<4096, 512>>>(Fx_re, Fx_im);
    fft_pass2<<<dim3(16, 128), 512>>>(256, 0);

    // Fy: [f=16][x=256][d=8][z=256]; pass1 along z, pass2 along x
    fft_pass1_flat<<<4096, 512>>>(Fy_re, Fy_im);
    fft_pass2<<<dim3(128, 16), 512>>>(2048, 1);

    // Fz: [f=16][x=256][y=256][d=8]; pass1 along y, pass2 along x
    fft_pass1_z<<<4096, 512>>>(Fz_re, Fz_im);
    fft_pass2<<<dim3(128, 16), 512>>>(2048, 2);

    gather_kernel<<<16384, 256>>>(pts, out);
}

// round 4
// speedup vs baseline: 1.2984x; 1.2984x over previous
#include <cuda_runtime.h>

// ---------------------------------------------------------------------------
//   volumes: 3 × [128 complex channels][256][256];  points: 131072 -> [N][16]
// ---------------------------------------------------------------------------

__device__ float g_alpha;
__device__ float g_twre[256];              // E[j] = exp(+2*pi*i*j/256)
__device__ float g_twim[256];
__device__ float g_tmp_re[8388608];        // 32 MB (pass-1 output, reused per volume)
__device__ float g_tmp_im[8388608];        // 32 MB
// Final sample volumes, interleaved complex: [H=256][W=256][C=128][re,im]
__device__ float g_vol[3][16777216];       // 3 × 64 MB

// base-4 digit reversal of an 8-bit index (256 = 4^4)
__device__ __forceinline__ int drev4(int k) {
    int r = (int)(__brev((unsigned)k) >> 24);
    return ((r >> 1) & 0x55) | ((r & 0x55) << 1);
}

// ---------------------------------------------------------------------------
__global__ void init_kernel(const float* __restrict__ alpha_params) {
    int t = threadIdx.x;
    if (t < 256) {
        float s, c;
        sincospif((float)t * (1.0f / 128.0f), &s, &c);   // 2*pi*t/256
        g_twre[t] = c;
        g_twim[t] = s;
    }
    if (t == 0) {
        float a  = alpha_params[0];
        float bx = 10.0f * a;
        g_alpha = (bx > 1.0f) ? a : 0.1f * log1pf(expf(fminf(bx, 30.0f)));
    }
}

// ---------------------------------------------------------------------------
// One radix-4 DIT butterfly, inverse (sign +), unnormalized.
// i0 = first element index in smem, dq = quarter-offset (incl. layout stride),
// t = pos * (256/L) twiddle base index.
// ---------------------------------------------------------------------------
__device__ __forceinline__ void bfly4(float* __restrict__ sre, float* __restrict__ sim,
                                      int i0, int dq,
                                      const float* __restrict__ twr,
                                      const float* __restrict__ twi, int t) {
    float ar0 = sre[i0],        ai0 = sim[i0];
    float ar1 = sre[i0 + dq],   ai1 = sim[i0 + dq];
    float ar2 = sre[i0 + 2*dq], ai2 = sim[i0 + 2*dq];
    float ar3 = sre[i0 + 3*dq], ai3 = sim[i0 + 3*dq];
    float w1r = twr[t],     w1i = twi[t];
    float w2r = twr[2 * t], w2i = twi[2 * t];
    float w3r = twr[3 * t], w3i = twi[3 * t];
    float b1r = ar1 * w1r - ai1 * w1i, b1i = ar1 * w1i + ai1 * w1r;
    float b2r = ar2 * w2r - ai2 * w2i, b2i = ar2 * w2i + ai2 * w2r;
    float b3r = ar3 * w3r - ai3 * w3i, b3i = ar3 * w3i + ai3 * w3r;
    float s02r = ar0 + b2r, s02i = ai0 + b2i;
    float d02r = ar0 - b2r, d02i = ai0 - b2i;
    float s13r = b1r + b3r, s13i = b1i + b3i;
    float d13r = b1r - b3r, d13i = b1i - b3i;
    sre[i0]        = s02r + s13r;  sim[i0]        = s02i + s13i;
    sre[i0 + dq]   = d02r - d13i;  sim[i0 + dq]   = d02i + d13r;
    sre[i0 + 2*dq] = s02r - s13r;  sim[i0 + 2*dq] = s02i - s13i;
    sre[i0 + 3*dq] = d02r + d13i;  sim[i0 + 3*dq] = d02i - d13r;
}

// ---------------------------------------------------------------------------
// Pass 1: FFT along the contiguous input axis, 8 lines of 256 per block.
// MODE 0 (Fx): rows [c][z], output row-major        -> g_tmp [c][y][z]
// MODE 1 (Fy): rows [d][z], output transposed [z][d] -> g_tmp [f][x][z][d]
// MODE 2 (Fz): input interleaved [y][d], output [y][d] -> g_tmp [f][x][y][d]
// smem rows padded to 257 floats for conflict-free transposed access.
// ---------------------------------------------------------------------------
template<int MODE>
__global__ __launch_bounds__(512) void fft_pass1(const float* __restrict__ in_re,
                                                 const float* __restrict__ in_im) {
    __shared__ float sre[8 * 257], sim[8 * 257];
    __shared__ float twr[256], twi[256];
    int tid = threadIdx.x;
    if (tid < 256) { twr[tid] = g_twre[tid]; twi[tid] = g_twim[tid]; }
    float alpha = g_alpha;
    int base = blockIdx.x << 11;                   // 8 * 256 elements
#pragma unroll
    for (int s = 0; s < 4; s++) {
        int idx = tid + (s << 9);
        int dst;
        if (MODE == 2) { int y = idx >> 3, d = idx & 7;     dst = d * 257 + drev4(y); }
        else           { int row = idx >> 8, k = idx & 255; dst = row * 257 + drev4(k); }
        sre[dst] = in_re[base + idx] * alpha;
        sim[dst] = in_im[base + idx] * alpha;
    }
    __syncthreads();
#pragma unroll
    for (int L = 4; L <= 256; L <<= 2) {
        int quarter = L >> 2;
        int tws = 256 / L;
        int row = tid >> 6, j = tid & 63;
        int grp = j / quarter, pos = j - grp * quarter;
        bfly4(sre, sim, row * 257 + grp * L + pos, quarter, twr, twi, pos * tws);
        __syncthreads();
    }
#pragma unroll
    for (int s = 0; s < 4; s++) {
        int idx = tid + (s << 9);
        float vr, vi;
        if (MODE == 0) { int row = idx >> 8, k = idx & 255; vr = sre[row * 257 + k]; vi = sim[row * 257 + k]; }
        else           { int z = idx >> 3, d = idx & 7;     vr = sre[d * 257 + z];   vi = sim[d * 257 + z]; }
        g_tmp_re[base + idx] = vr;
        g_tmp_im[base + idx] = vi;
    }
}

// ---------------------------------------------------------------------------
// Pass 2: FFT along the strided (middle) axis + layout transform into g_vol.
// g_tmp viewed as [O][256][I]:
//  VID 0 (Fx): O=128 (c), I=256 (z).  Block = 4 c's × 4 z's (16 lines).
//              Store: texel (h=k, w=z), 4 consecutive c -> 32B contiguous.
//  VID 1 (Fy): O=16 (f), I=2048 (z,d innermost). Block = 1 f × 16 i.
//              Store: texel (h=k(x), w=z), c=8f+d, d=0..7 -> 64B contiguous.
//  VID 2 (Fz): O=16 (f), I=2048 (y,d innermost). Same, texel (h=y, w=k(x)).
// smem tile: [256 k][16 lines] stride 17 (conflict-free).
// ---------------------------------------------------------------------------
template<int VID>
__global__ __launch_bounds__(512) void fft_pass2() {
    __shared__ float sre[256 * 17], sim[256 * 17];
    __shared__ float twr[256], twi[256];
    int tid = threadIdx.x;
    if (tid < 256) { twr[tid] = g_twre[tid]; twi[tid] = g_twim[tid]; }
    int oy = blockIdx.y;
#pragma unroll
    for (int s = 0; s < 8; s++) {
        int idx = tid + (s << 9);
        int k = idx >> 4, l = idx & 15;
        int src;
        if (VID == 0) {
            int o0 = oy << 2, i0 = blockIdx.x << 2;
            src = (o0 + (l >> 2)) * 65536 + k * 256 + i0 + (l & 3);
        } else {
            src = oy * 524288 + k * 2048 + (blockIdx.x << 4) + l;
        }
        int dst = drev4(k) * 17 + l;
        sre[dst] = g_tmp_re[src];
        sim[dst] = g_tmp_im[src];
    }
    __syncthreads();
#pragma unroll
    for (int L = 4; L <= 256; L <<= 2) {
        int quarter = L >> 2;
        int tws = 256 / L;
#pragma unroll
        for (int s = 0; s < 2; s++) {
            int bi = tid + (s << 9);
            int l = bi & 15, j = bi >> 4;
            int grp = j / quarter, pos = j - grp * quarter;
            bfly4(sre, sim, (grp * L + pos) * 17 + l, quarter * 17, twr, twi, pos * tws);
        }
        __syncthreads();
    }
    float4* vol4 = reinterpret_cast<float4*>(g_vol[VID]);
    if (VID == 0) {
        int o0 = oy << 2, i0 = blockIdx.x << 2;
#pragma unroll
        for (int u0 = 0; u0 < 2; u0++) {
            int u = tid + (u0 << 9);
            int k = u >> 2, iz = u & 3;
            int sb = k * 17 + iz;
            float4* vp = vol4 + (((k << 8) + i0 + iz) << 6) + (o0 >> 1);
            vp[0] = make_float4(sre[sb],     sim[sb],     sre[sb + 4],  sim[sb + 4]);
            vp[1] = make_float4(sre[sb + 8], sim[sb + 8], sre[sb + 12], sim[sb + 12]);
        }
    } else {
        int k = tid >> 1, zt = tid & 1;
        int sb = k * 17 + zt * 8;
        int z = (blockIdx.x << 1) + zt;
        int texel = (VID == 1) ? ((k << 8) + z) : ((z << 8) + k);
        float4* vp = vol4 + (texel << 6) + (oy << 2);
#pragma unroll
        for (int j = 0; j < 4; j++)
            vp[j] = make_float4(sre[sb + 2 * j],     sim[sb + 2 * j],
                                sre[sb + 2 * j + 1], sim[sb + 2 * j + 1]);
    }
}

// ---------------------------------------------------------------------------
// Gather: one warp per point. Lane L owns channels c = 4L..4L+3.
// Each tap = 1 KB contiguous (2x float4 per lane). Twiddles: lanes 0..23
// compute sincospif once, distributed by shuffle. Pair-reduce -> 16 outputs.
// ---------------------------------------------------------------------------
__global__ __launch_bounds__(256) void gather_kernel(const float* __restrict__ pts,
                                                     float* __restrict__ out) {
    int warp = (blockIdx.x << 3) + (threadIdx.x >> 5);
    int lane = threadIdx.x & 31;

    const float px = pts[warp * 3 + 0];
    const float py = pts[warp * 3 + 1];
    const float pz = pts[warp * 3 + 2];

    float cval, sval;
    {
        int a = lane >> 3, d = lane & 7;
        float q  = (a == 0) ? px : ((a == 1) ? py : pz);
        float xx = (q + 1.0f) * (0.5f * 255.0f / 256.0f);
        float s_, c_;
        sincospif(2.0f * xx * (float)d, &s_, &c_);
        float sc = d ? 2.0f : 1.0f;
        cval = c_ * sc;
        sval = s_ * sc;
    }

    int q0[3], q1[3]; float wf[3];
    {
        float qv[3] = { px, py, pz };
#pragma unroll
        for (int a = 0; a < 3; a++) {
            float ii = (qv[a] + 1.0f) * 127.5f;
            float f0 = floorf(ii);
            wf[a] = ii - f0;
            int i0 = (int)f0;
            i0 = max(0, min(255, i0));
            q0[a] = i0;
            q1[a] = min(i0 + 1, 255);
        }
    }

    float acc = 0.0f;
    int dhalf = (lane & 1) << 2;
#pragma unroll
    for (int v = 0; v < 3; v++) {
        int h0, h1, w0, w1; float wy, wx;
        if (v == 0)      { h0 = q0[1]; h1 = q1[1]; wy = wf[1]; w0 = q0[2]; w1 = q1[2]; wx = wf[2]; }
        else if (v == 1) { h0 = q0[0]; h1 = q1[0]; wy = wf[0]; w0 = q0[2]; w1 = q1[2]; wx = wf[2]; }
        else             { h0 = q0[1]; h1 = q1[1]; wy = wf[1]; w0 = q0[0]; w1 = q1[0]; wx = wf[0]; }
        float w00 = (1.0f - wy) * (1.0f - wx);
        float w01 = (1.0f - wy) * wx;
        float w10 = wy * (1.0f - wx);
        float w11 = wy * wx;

        const float4* V = reinterpret_cast<const float4*>(g_vol[v]);
        int b00 = (((h0 << 8) + w0) << 6) + (lane << 1);
        int b01 = (((h0 << 8) + w1) << 6) + (lane << 1);
        int b10 = (((h1 << 8) + w0) << 6) + (lane << 1);
        int b11 = (((h1 << 8) + w1) << 6) + (lane << 1);

        float rr0 = 0, ri0 = 0, rr1 = 0, ri1 = 0, rr2 = 0, ri2 = 0, rr3 = 0, ri3 = 0;
        {
            float4 a = V[b00], b = V[b00 + 1];
            rr0 += w00 * a.x; ri0 += w00 * a.y; rr1 += w00 * a.z; ri1 += w00 * a.w;
            rr2 += w00 * b.x; ri2 += w00 * b.y; rr3 += w00 * b.z; ri3 += w00 * b.w;
        }
        {
            float4 a = V[b01], b = V[b01 + 1];
            rr0 += w01 * a.x; ri0 += w01 * a.y; rr1 += w01 * a.z; ri1 += w01 * a.w;
            rr2 += w01 * b.x; ri2 += w01 * b.y; rr3 += w01 * b.z; ri3 += w01 * b.w;
        }
        {
            float4 a = V[b10], b = V[b10 + 1];
            rr0 += w10 * a.x; ri0 += w10 * a.y; rr1 += w10 * a.z; ri1 += w10 * a.w;
            rr2 += w10 * b.x; ri2 += w10 * b.y; rr3 += w10 * b.z; ri3 += w10 * b.w;
        }
        {
            float4 a = V[b11], b = V[b11 + 1];
            rr0 += w11 * a.x; ri0 += w11 * a.y; rr1 += w11 * a.z; ri1 += w11 * a.w;
            rr2 += w11 * b.x; ri2 += w11 * b.y; rr3 += w11 * b.z; ri3 += w11 * b.w;
        }

        int sb = (v << 3) + dhalf;
        float tc0 = __shfl_sync(0xffffffffu, cval, sb + 0);
        float ts0 = __shfl_sync(0xffffffffu, sval, sb + 0);
        float tc1 = __shfl_sync(0xffffffffu, cval, sb + 1);
        float ts1 = __shfl_sync(0xffffffffu, sval, sb + 1);
        float tc2 = __shfl_sync(0xffffffffu, cval, sb + 2);
        float ts2 = __shfl_sync(0xffffffffu, sval, sb + 2);
        float tc3 = __shfl_sync(0xffffffffu, cval, sb + 3);
        float ts3 = __shfl_sync(0xffffffffu, sval, sb + 3);

        acc += rr0 * tc0 - ri0 * ts0;
        acc += rr1 * tc1 - ri1 * ts1;
        acc += rr2 * tc2 - ri2 * ts2;
        acc += rr3 * tc3 - ri3 * ts3;
    }

    acc += __shfl_xor_sync(0xffffffffu, acc, 1);
    if ((lane & 1) == 0) out[(warp << 4) + (lane >> 1)] = acc;
}

// ---------------------------------------------------------------------------
extern "C" void kernel_launch(void* const* d_in, const int* in_sizes, int n_in,
                              void* d_out, int out_size) {
    const float* pts   = (const float*)d_in[0];
    const float* Fx_re = (const float*)d_in[1];
    const float* Fx_im = (const float*)d_in[2];
    const float* Fy_re = (const float*)d_in[3];
    const float* Fy_im = (const float*)d_in[4];
    const float* Fz_re = (const float*)d_in[5];
    const float* Fz_im = (const float*)d_in[6];
    const float* ap    = (const float*)d_in[7];
    float* out = (float*)d_out;

    init_kernel<<<1, 256>>>(ap);

    // Fx: [c=128][y][z]; pass1 along z (row-major out), pass2 along y
    fft_pass1<0><<<4096, 512>>>(Fx_re, Fx_im);
    fft_pass2<0><<<dim3(64, 32), 512>>>();

    // Fy: [f][x][d][z]; pass1 along z (out [z][d]), pass2 along x
    fft_pass1<1><<<4096, 512>>>(Fy_re, Fy_im);
    fft_pass2<1><<<dim3(128, 16), 512>>>();

    // Fz: [f][x][y][d]; pass1 along y (out [y][d]), pass2 along x
    fft_pass1<2><<<4096, 512>>>(Fz_re, Fz_im);
    fft_pass2<2><<<dim3(128, 16), 512>>>();

    gather_kernel<<<16384, 256>>>(pts, out);
}

// round 5
// speedup vs baseline: 2.0375x; 1.5692x over previous
#include <cuda_runtime.h>

// ---------------------------------------------------------------------------
//   volumes: 3 × [128 complex channels][256][256];  points: 131072 -> [N][16]
//   FFT engine: four-step 256 = 16 x 16, register FFT16s, conflict-free smem.
// ---------------------------------------------------------------------------

__device__ float g_alpha;
__device__ float g_twre[256];              // W256^j = exp(+2*pi*i*j/256)
__device__ float g_twim[256];
__device__ float g_tmp_re[8388608];        // 32 MB (pass-1 output, reused per volume)
__device__ float g_tmp_im[8388608];
// Final sample volumes, interleaved complex: [H=256][W=256][C=128][re,im]
__device__ float g_vol[3][16777216];       // 3 × 64 MB

// smem layout (dynamic): sre[8448] | sim[8448] | twr[256] | twi[256]
#define SM_STRIDE 33
#define SM_ELEMS  8448
#define SM_FLOATS (2 * SM_ELEMS + 512)
#define SM_BYTES  (SM_FLOATS * 4)

// ---------------------------------------------------------------------------
__global__ void init_kernel(const float* __restrict__ alpha_params) {
    int t = threadIdx.x;
    if (t < 256) {
        float s, c;
        sincospif((float)t * (1.0f / 128.0f), &s, &c);   // 2*pi*t/256
        g_twre[t] = c;
        g_twim[t] = s;
    }
    if (t == 0) {
        float a  = alpha_params[0];
        float bx = 10.0f * a;
        g_alpha = (bx > 1.0f) ? a : 0.1f * log1pf(expf(fminf(bx, 30.0f)));
    }
}

// ---------------------------------------------------------------------------
// 16-point inverse DFT (sign +, unnormalized), DIF radix-4, all in registers.
// Natural-order input v[0..15]; output X16[4q+r] lands in slot [4r+q].
// ---------------------------------------------------------------------------
#define C1_ 0.92387953251128675613f
#define S1_ 0.38268343236508977173f
#define R2_ 0.70710678118654752440f

__device__ __forceinline__ void fft16_reg(float* vr, float* vi) {
    // Stage A: 4-pt DFTs over s on {m, m+4, m+8, m+12}; b_r -> slot m + 4r.
#pragma unroll
    for (int m = 0; m < 4; m++) {
        float t0r = vr[m]   + vr[m+8],  t0i = vi[m]   + vi[m+8];
        float t2r = vr[m]   - vr[m+8],  t2i = vi[m]   - vi[m+8];
        float t1r = vr[m+4] + vr[m+12], t1i = vi[m+4] + vi[m+12];
        float t3r = vr[m+4] - vr[m+12], t3i = vi[m+4] - vi[m+12];
        vr[m]    = t0r + t1r;  vi[m]    = t0i + t1i;
        vr[m+4]  = t2r - t3i;  vi[m+4]  = t2i + t3r;   // t2 + i*t3
        vr[m+8]  = t0r - t1r;  vi[m+8]  = t0i - t1i;
        vr[m+12] = t2r + t3i;  vi[m+12] = t2i - t3r;   // t2 - i*t3
    }
    // Twiddle W16^{r*pos} on slot 4r+pos (inverse sign: +i direction)
    const float TWR[16] = {1,1,1,1,  1,C1_,R2_,S1_,  1,R2_,0.f,-R2_,  1,S1_,-R2_,-C1_};
    const float TWI[16] = {0,0,0,0,  0,S1_,R2_,C1_,  0,R2_,1.f, R2_,  0,C1_, R2_,-S1_};
#pragma unroll
    for (int s = 5; s < 16; s++) {
        if ((s & 3) == 0) continue;   // pos = 0 -> twiddle 1
        float wr = TWR[s], wi = TWI[s];
        float xr = vr[s], xi = vi[s];
        vr[s] = xr * wr - xi * wi;
        vi[s] = xr * wi + xi * wr;
    }
    // Stage B: 4-pt DFTs over pos within each r-group (no twiddle)
#pragma unroll
    for (int r = 0; r < 4; r++) {
        int b = 4 * r;
        float t0r = vr[b]   + vr[b+2], t0i = vi[b]   + vi[b+2];
        float t2r = vr[b]   - vr[b+2], t2i = vi[b]   - vi[b+2];
        float t1r = vr[b+1] + vr[b+3], t1i = vi[b+1] + vi[b+3];
        float t3r = vr[b+1] - vr[b+3], t3i = vi[b+1] - vi[b+3];
        vr[b]   = t0r + t1r; vi[b]   = t0i + t1i;
        vr[b+1] = t2r - t3i; vi[b+1] = t2i + t3r;
        vr[b+2] = t0r - t1r; vi[b+2] = t0i - t1i;
        vr[b+3] = t2r + t3i; vi[b+3] = t2i - t3r;
    }
}

// ---------------------------------------------------------------------------
// Four-step 256-pt inverse FFT on 32 lines held in smem (element m of line l
// at sre/sim[m*33 + l]). Thread role: t = tid>>5 (warp id, 0..15), l = lane.
// Every smem access within a warp differs only in l -> conflict-free.
// Requires data loaded; leaves natural-order result in the same buffer.
// ---------------------------------------------------------------------------
__device__ __forceinline__ void fft256_lines(float* sre, float* sim,
                                             const float* twr, const float* twi,
                                             int l, int t) {
    float vr[16], vi[16];
    // Step 1: v[n1] = x[16*n1 + t];  FFT16 over n1 -> A[k1] in slot 4r+q.
#pragma unroll
    for (int n1 = 0; n1 < 16; n1++) {
        int idx = (16 * n1 + t) * SM_STRIDE + l;
        vr[n1] = sre[idx]; vi[n1] = sim[idx];
    }
    fft16_reg(vr, vi);
    // Step 2: B[k1] = A[k1] * W256^{t*k1}  (k1 = 4*(s&3) + (s>>2))
#pragma unroll
    for (int s = 0; s < 16; s++) {
        int k1 = 4 * (s & 3) + (s >> 2);
        int e = (t * k1) & 255;
        float wr = twr[e], wi = twi[e];      // warp-uniform -> broadcast
        float xr = vr[s], xi = vi[s];
        vr[s] = xr * wr - xi * wi;
        vi[s] = xr * wi + xi * wr;
    }
    __syncthreads();                          // all step-1 reads done
    // Transpose write: elem(16*k1 + t) = B[k1]
#pragma unroll
    for (int s = 0; s < 16; s++) {
        int k1 = 4 * (s & 3) + (s >> 2);
        int idx = (16 * k1 + t) * SM_STRIDE + l;
        sre[idx] = vr[s]; sim[idx] = vi[s];
    }
    __syncthreads();
    // Step 3: v[n2] = B[k1=t, n2] = elem(16*t + n2); FFT16 over n2.
#pragma unroll
    for (int n2 = 0; n2 < 16; n2++) {
        int idx = (16 * t + n2) * SM_STRIDE + l;
        vr[n2] = sre[idx]; vi[n2] = sim[idx];
    }
    fft16_reg(vr, vi);
    __syncthreads();                          // all step-3 reads done
    // Output: X[16*k2 + t], k2 = 4*(s&3)+(s>>2) -> natural order in buffer.
#pragma unroll
    for (int s = 0; s < 16; s++) {
        int k2 = 4 * (s & 3) + (s >> 2);
        int idx = (16 * k2 + t) * SM_STRIDE + l;
        sre[idx] = vr[s]; sim[idx] = vi[s];
    }
    __syncthreads();
}

// ---------------------------------------------------------------------------
// Pass 1: FFT along the contiguous input axis; 32 lines of 256 per block.
// MODE 0 (Fx): lines (c,y) over z; in/out row-major   -> g_tmp [c][y][z]
// MODE 1 (Fy): lines (f,x,d) over z; out [z][d]       -> g_tmp [f][x][z][d]
// MODE 2 (Fz): in/out interleaved [y][d] per (f,x)    -> g_tmp [f][x][y][d]
// ---------------------------------------------------------------------------
template<int MODE>
__global__ __launch_bounds__(512) void fft_pass1(const float* __restrict__ in_re,
                                                 const float* __restrict__ in_im) {
    extern __shared__ float smem[];
    float* sre = smem;
    float* sim = smem + SM_ELEMS;
    float* twr = smem + 2 * SM_ELEMS;
    float* twi = twr + 256;
    int tid = threadIdx.x;
    if (tid < 256) { twr[tid] = g_twre[tid]; twi[tid] = g_twim[tid]; }
    float alpha = g_alpha;
    long long base = (long long)blockIdx.x << 13;          // 32 lines * 256
    // Phase 1: coalesced load -> smem [m][line]
#pragma unroll
    for (int s = 0; s < 16; s++) {
        int idx = tid + (s << 9);
        int m, rl;
        if (MODE == 2) { m = (idx >> 3) & 255; rl = ((idx >> 11) << 3) | (idx & 7); }
        else           { m = idx & 255;        rl = idx >> 8; }
        sre[m * SM_STRIDE + rl] = in_re[base + idx] * alpha;
        sim[m * SM_STRIDE + rl] = in_im[base + idx] * alpha;
    }
    __syncthreads();
    fft256_lines(sre, sim, twr, twi, tid & 31, tid >> 5);
    // Phase 5: coalesced store with MODE output mapping
#pragma unroll
    for (int s = 0; s < 16; s++) {
        int idx = tid + (s << 9);
        float vr, vi;
        if (MODE == 0) {
            vr = sre[(idx & 255) * SM_STRIDE + (idx >> 8)];
            vi = sim[(idx & 255) * SM_STRIDE + (idx >> 8)];
        } else {
            // out offset idx == fx_rel*2048 + m*8 + d  (m = z or y)
            int fx8 = (idx >> 11) << 3, m = (idx >> 3) & 255, d = idx & 7;
            vr = sre[m * SM_STRIDE + fx8 + d];
            vi = sim[m * SM_STRIDE + fx8 + d];
        }
        g_tmp_re[base + idx] = vr;
        g_tmp_im[base + idx] = vi;
    }
}

// ---------------------------------------------------------------------------
// Pass 2: FFT along the strided axis of g_tmp + layout transform into g_vol.
//  VID 0 (Fx): g_tmp [c][y][z]; block = 4 c x 8 z, FFT over y.
//              texel (h=y, w=z): 4 consecutive c -> 2x float4 (32B bursts).
//  VID 1 (Fy): g_tmp [f][x][z][d]; block = 1 f x 32 i (4 z x 8 d), FFT over x.
//              texel (h=x, w=z): c=8f+d, 8 d -> 4x float4 (64B bursts).
//  VID 2 (Fz): g_tmp [f][x][y][d]; same, texel (h=y, w=x).
// ---------------------------------------------------------------------------
template<int VID>
__global__ __launch_bounds__(512) void fft_pass2() {
    extern __shared__ float smem[];
    float* sre = smem;
    float* sim = smem + SM_ELEMS;
    float* twr = smem + 2 * SM_ELEMS;
    float* twi = twr + 256;
    int tid = threadIdx.x;
    if (tid < 256) { twr[tid] = g_twre[tid]; twi[tid] = g_twim[tid]; }
    // Phase 1: coalesced load
    if (VID == 0) {
        int c0 = blockIdx.y << 2, z0 = blockIdx.x << 3;
#pragma unroll
        for (int s = 0; s < 16; s++) {
            int u = tid + (s << 9);
            int zs = u & 7, cs = (u >> 3) & 3, k = u >> 5;
            int src = (c0 + cs) * 65536 + k * 256 + z0 + zs;
            int rl = (cs << 3) + zs;
            sre[k * SM_STRIDE + rl] = g_tmp_re[src];
            sim[k * SM_STRIDE + rl] = g_tmp_im[src];
        }
    } else {
        int f = blockIdx.y, i0 = blockIdx.x << 5;
#pragma unroll
        for (int s = 0; s < 16; s++) {
            int u = tid + (s << 9);
            int rl = u & 31, k = u >> 5;
            int src = f * 524288 + k * 2048 + i0 + rl;
            sre[k * SM_STRIDE + rl] = g_tmp_re[src];
            sim[k * SM_STRIDE + rl] = g_tmp_im[src];
        }
    }
    __syncthreads();
    fft256_lines(sre, sim, twr, twi, tid & 31, tid >> 5);
    // Phase 5: store to g_vol with contiguous bursts
    float4* vol4 = reinterpret_cast<float4*>(g_vol[VID]);
    if (VID == 0) {
        int c0 = blockIdx.y << 2, z0 = blockIdx.x << 3;
#pragma unroll
        for (int s = 0; s < 8; s++) {
            int u = tid + (s << 9);
            int j = u & 1, zs = (u >> 1) & 7, k = u >> 4;
            int sb = k * SM_STRIDE + zs;
            float e0 = sre[sb + ((2*j)   << 3)], o0 = sim[sb + ((2*j)   << 3)];
            float e1 = sre[sb + ((2*j+1) << 3)], o1 = sim[sb + ((2*j+1) << 3)];
            int texel = (k << 8) + z0 + zs;
            vol4[(texel << 6) + (c0 >> 1) + j] = make_float4(e0, o0, e1, o1);
        }
    } else {
        int f = blockIdx.y, i0 = blockIdx.x << 5;
        int w0 = i0 >> 3;                      // first z (VID1) or y (VID2)
#pragma unroll
        for (int s = 0; s < 8; s++) {
            int u = tid + (s << 9);
            int j = u & 3, zz = (u >> 2) & 3, k = u >> 4;
            int sb = k * SM_STRIDE + (zz << 3);
            float e0 = sre[sb + 2*j],     o0 = sim[sb + 2*j];
            float e1 = sre[sb + 2*j + 1], o1 = sim[sb + 2*j + 1];
            int texel = (VID == 1) ? ((k << 8) + w0 + zz)
                                   : (((w0 + zz) << 8) + k);
            vol4[(texel << 6) + (f << 2) + j] = make_float4(e0, o0, e1, o1);
        }
    }
}

// ---------------------------------------------------------------------------
// Gather: one warp per point (unchanged from validated R2/R4 kernel).
// ---------------------------------------------------------------------------
__global__ __launch_bounds__(256) void gather_kernel(const float* __restrict__ pts,
                                                     float* __restrict__ out) {
    int warp = (blockIdx.x << 3) + (threadIdx.x >> 5);
    int lane = threadIdx.x & 31;

    const float px = pts[warp * 3 + 0];
    const float py = pts[warp * 3 + 1];
    const float pz = pts[warp * 3 + 2];

    float cval, sval;
    {
        int a = lane >> 3, d = lane & 7;
        float q  = (a == 0) ? px : ((a == 1) ? py : pz);
        float xx = (q + 1.0f) * (0.5f * 255.0f / 256.0f);
        float s_, c_;
        sincospif(2.0f * xx * (float)d, &s_, &c_);
        float sc = d ? 2.0f : 1.0f;
        cval = c_ * sc;
        sval = s_ * sc;
    }

    int q0[3], q1[3]; float wf[3];
    {
        float qv[3] = { px, py, pz };
#pragma unroll
        for (int a = 0; a < 3; a++) {
            float ii = (qv[a] + 1.0f) * 127.5f;
            float f0 = floorf(ii);
            wf[a] = ii - f0;
            int i0 = (int)f0;
            i0 = max(0, min(255, i0));
            q0[a] = i0;
            q1[a] = min(i0 + 1, 255);
        }
    }

    float acc = 0.0f;
    int dhalf = (lane & 1) << 2;
#pragma unroll
    for (int v = 0; v < 3; v++) {
        int h0, h1, w0, w1; float wy, wx;
        if (v == 0)      { h0 = q0[1]; h1 = q1[1]; wy = wf[1]; w0 = q0[2]; w1 = q1[2]; wx = wf[2]; }
        else if (v == 1) { h0 = q0[0]; h1 = q1[0]; wy = wf[0]; w0 = q0[2]; w1 = q1[2]; wx = wf[2]; }
        else             { h0 = q0[1]; h1 = q1[1]; wy = wf[1]; w0 = q0[0]; w1 = q1[0]; wx = wf[0]; }
        float w00 = (1.0f - wy) * (1.0f - wx);
        float w01 = (1.0f - wy) * wx;
        float w10 = wy * (1.0f - wx);
        float w11 = wy * wx;

        const float4* V = reinterpret_cast<const float4*>(g_vol[v]);
        int b00 = (((h0 << 8) + w0) << 6) + (lane << 1);
        int b01 = (((h0 << 8) + w1) << 6) + (lane << 1);
        int b10 = (((h1 << 8) + w0) << 6) + (lane << 1);
        int b11 = (((h1 << 8) + w1) << 6) + (lane << 1);

        float rr0 = 0, ri0 = 0, rr1 = 0, ri1 = 0, rr2 = 0, ri2 = 0, rr3 = 0, ri3 = 0;
        {
            float4 a = V[b00], b = V[b00 + 1];
            rr0 += w00 * a.x; ri0 += w00 * a.y; rr1 += w00 * a.z; ri1 += w00 * a.w;
            rr2 += w00 * b.x; ri2 += w00 * b.y; rr3 += w00 * b.z; ri3 += w00 * b.w;
        }
        {
            float4 a = V[b01], b = V[b01 + 1];
            rr0 += w01 * a.x; ri0 += w01 * a.y; rr1 += w01 * a.z; ri1 += w01 * a.w;
            rr2 += w01 * b.x; ri2 += w01 * b.y; rr3 += w01 * b.z; ri3 += w01 * b.w;
        }
        {
            float4 a = V[b10], b = V[b10 + 1];
            rr0 += w10 * a.x; ri0 += w10 * a.y; rr1 += w10 * a.z; ri1 += w10 * a.w;
            rr2 += w10 * b.x; ri2 += w10 * b.y; rr3 += w10 * b.z; ri3 += w10 * b.w;
        }
        {
            float4 a = V[b11], b = V[b11 + 1];
            rr0 += w11 * a.x; ri0 += w11 * a.y; rr1 += w11 * a.z; ri1 += w11 * a.w;
            rr2 += w11 * b.x; ri2 += w11 * b.y; rr3 += w11 * b.z; ri3 += w11 * b.w;
        }

        int sb = (v << 3) + dhalf;
        float tc0 = __shfl_sync(0xffffffffu, cval, sb + 0);
        float ts0 = __shfl_sync(0xffffffffu, sval, sb + 0);
        float tc1 = __shfl_sync(0xffffffffu, cval, sb + 1);
        float ts1 = __shfl_sync(0xffffffffu, sval, sb + 1);
        float tc2 = __shfl_sync(0xffffffffu, cval, sb + 2);
        float ts2 = __shfl_sync(0xffffffffu, sval, sb + 2);
        float tc3 = __shfl_sync(0xffffffffu, cval, sb + 3);
        float ts3 = __shfl_sync(0xffffffffu, sval, sb + 3);

        acc += rr0 * tc0 - ri0 * ts0;
        acc += rr1 * tc1 - ri1 * ts1;
        acc += rr2 * tc2 - ri2 * ts2;
        acc += rr3 * tc3 - ri3 * ts3;
    }

    acc += __shfl_xor_sync(0xffffffffu, acc, 1);
    if ((lane & 1) == 0) out[(warp << 4) + (lane >> 1)] = acc;
}

// ---------------------------------------------------------------------------
extern "C" void kernel_launch(void* const* d_in, const int* in_sizes, int n_in,
                              void* d_out, int out_size) {
    const float* pts   = (const float*)d_in[0];
    const float* Fx_re = (const float*)d_in[1];
    const float* Fx_im = (const float*)d_in[2];
    const float* Fy_re = (const float*)d_in[3];
    const float* Fy_im = (const float*)d_in[4];
    const float* Fz_re = (const float*)d_in[5];
    const float* Fz_im = (const float*)d_in[6];
    const float* ap    = (const float*)d_in[7];
    float* out = (float*)d_out;

    // Allow >48KB dynamic smem (idempotent; no allocation involved)
    cudaFuncSetAttribute(fft_pass1<0>, cudaFuncAttributeMaxDynamicSharedMemorySize, SM_BYTES);
    cudaFuncSetAttribute(fft_pass1<1>, cudaFuncAttributeMaxDynamicSharedMemorySize, SM_BYTES);
    cudaFuncSetAttribute(fft_pass1<2>, cudaFuncAttributeMaxDynamicSharedMemorySize, SM_BYTES);
    cudaFuncSetAttribute(fft_pass2<0>, cudaFuncAttributeMaxDynamicSharedMemorySize, SM_BYTES);
    cudaFuncSetAttribute(fft_pass2<1>, cudaFuncAttributeMaxDynamicSharedMemorySize, SM_BYTES);
    cudaFuncSetAttribute(fft_pass2<2>, cudaFuncAttributeMaxDynamicSharedMemorySize, SM_BYTES);

    init_kernel<<<1, 256>>>(ap);

    // Fx: [c=128][y][z]; pass1 along z, pass2 along y
    fft_pass1<0><<<1024, 512, SM_BYTES>>>(Fx_re, Fx_im);
    fft_pass2<0><<<dim3(32, 32), 512, SM_BYTES>>>();

    // Fy: [f][x][d][z]; pass1 along z (out [z][d]), pass2 along x
    fft_pass1<1><<<1024, 512, SM_BYTES>>>(Fy_re, Fy_im);
    fft_pass2<1><<<dim3(64, 16), 512, SM_BYTES>>>();

    // Fz: [f][x][y][d]; pass1 along y (out [y][d]), pass2 along x
    fft_pass1<2><<<1024, 512, SM_BYTES>>>(Fz_re, Fz_im);
    fft_pass2<2><<<dim3(64, 16), 512, SM_BYTES>>>();

    gather_kernel<<<16384, 256>>>(pts, out);
}

// round 14
// speedup vs baseline: 2.5667x; 1.2598x over previous
#include <cuda_runtime.h>
#include <cuda_fp16.h>

// ---------------------------------------------------------------------------
//   volumes: 3 × [128 complex channels][256][256];  points: 131072 -> [N][16]
//   FFT engine: four-step 256 = 16 x 16, register FFT16s, conflict-free smem.
//   Sample volumes stored fp16 (half2 re,im): 3 x 32 MB -> fits L2.
// ---------------------------------------------------------------------------

__device__ float g_alpha;
__device__ float g_twre[256];              // W256^j = exp(+2*pi*i*j/256)
__device__ float g_twim[256];
__device__ float g_tmp_re[8388608];        // 32 MB (pass-1 output, reused per volume)
__device__ float g_tmp_im[8388608];
// Final sample volumes, fp16 interleaved: [H=256][W=256][C=128] half2(re,im)
__device__ __half2 g_volh[3][8388608];     // 3 × 32 MB

// smem layout (dynamic): sre[8448] | sim[8448] | twr[256] | twi[256]
#define SM_STRIDE 33
#define SM_ELEMS  8448
#define SM_FLOATS (2 * SM_ELEMS + 512)
#define SM_BYTES  (SM_FLOATS * 4)

// ---------------------------------------------------------------------------
__global__ void init_kernel(const float* __restrict__ alpha_params) {
    int t = threadIdx.x;
    if (t < 256) {
        float s, c;
        sincospif((float)t * (1.0f / 128.0f), &s, &c);   // 2*pi*t/256
        g_twre[t] = c;
        g_twim[t] = s;
    }
    if (t == 0) {
        float a  = alpha_params[0];
        float bx = 10.0f * a;
        g_alpha = (bx > 1.0f) ? a : 0.1f * log1pf(expf(fminf(bx, 30.0f)));
    }
}

// ---------------------------------------------------------------------------
// 16-point inverse DFT (sign +, unnormalized), DIF radix-4, all in registers.
// Natural-order input v[0..15]; output X16[4q+r] lands in slot [4r+q].
// ---------------------------------------------------------------------------
#define C1_ 0.92387953251128675613f
#define S1_ 0.38268343236508977173f
#define R2_ 0.70710678118654752440f

__device__ __forceinline__ void fft16_reg(float* vr, float* vi) {
#pragma unroll
    for (int m = 0; m < 4; m++) {
        float t0r = vr[m]   + vr[m+8],  t0i = vi[m]   + vi[m+8];
        float t2r = vr[m]   - vr[m+8],  t2i = vi[m]   - vi[m+8];
        float t1r = vr[m+4] + vr[m+12], t1i = vi[m+4] + vi[m+12];
        float t3r = vr[m+4] - vr[m+12], t3i = vi[m+4] - vi[m+12];
        vr[m]    = t0r + t1r;  vi[m]    = t0i + t1i;
        vr[m+4]  = t2r - t3i;  vi[m+4]  = t2i + t3r;   // t2 + i*t3
        vr[m+8]  = t0r - t1r;  vi[m+8]  = t0i - t1i;
        vr[m+12] = t2r + t3i;  vi[m+12] = t2i - t3r;   // t2 - i*t3
    }
    const float TWR[16] = {1,1,1,1,  1,C1_,R2_,S1_,  1,R2_,0.f,-R2_,  1,S1_,-R2_,-C1_};
    const float TWI[16] = {0,0,0,0,  0,S1_,R2_,C1_,  0,R2_,1.f, R2_,  0,C1_, R2_,-S1_};
#pragma unroll
    for (int s = 5; s < 16; s++) {
        if ((s & 3) == 0) continue;   // pos = 0 -> twiddle 1
        float wr = TWR[s], wi = TWI[s];
        float xr = vr[s], xi = vi[s];
        vr[s] = xr * wr - xi * wi;
        vi[s] = xr * wi + xi * wr;
    }
#pragma unroll
    for (int r = 0; r < 4; r++) {
        int b = 4 * r;
        float t0r = vr[b]   + vr[b+2], t0i = vi[b]   + vi[b+2];
        float t2r = vr[b]   - vr[b+2], t2i = vi[b]   - vi[b+2];
        float t1r = vr[b+1] + vr[b+3], t1i = vi[b+1] + vi[b+3];
        float t3r = vr[b+1] - vr[b+3], t3i = vi[b+1] - vi[b+3];
        vr[b]   = t0r + t1r; vi[b]   = t0i + t1i;
        vr[b+1] = t2r - t3i; vi[b+1] = t2i + t3r;
        vr[b+2] = t0r - t1r; vi[b+2] = t0i - t1i;
        vr[b+3] = t2r + t3i; vi[b+3] = t2i - t3r;
    }
}

// ---------------------------------------------------------------------------
// Four-step 256-pt inverse FFT on 32 lines held in smem (element m of line l
// at sre/sim[m*33 + l]). t = tid>>5 (warp id), l = lane. Conflict-free.
// ---------------------------------------------------------------------------
__device__ __forceinline__ void fft256_lines(float* sre, float* sim,
                                             const float* twr, const float* twi,
                                             int l, int t) {
    float vr[16], vi[16];
#pragma unroll
    for (int n1 = 0; n1 < 16; n1++) {
        int idx = (16 * n1 + t) * SM_STRIDE + l;
        vr[n1] = sre[idx]; vi[n1] = sim[idx];
    }
    fft16_reg(vr, vi);
#pragma unroll
    for (int s = 0; s < 16; s++) {
        int k1 = 4 * (s & 3) + (s >> 2);
        int e = (t * k1) & 255;
        float wr = twr[e], wi = twi[e];      // warp-uniform -> broadcast
        float xr = vr[s], xi = vi[s];
        vr[s] = xr * wr - xi * wi;
        vi[s] = xr * wi + xi * wr;
    }
    __syncthreads();
#pragma unroll
    for (int s = 0; s < 16; s++) {
        int k1 = 4 * (s & 3) + (s >> 2);
        int idx = (16 * k1 + t) * SM_STRIDE + l;
        sre[idx] = vr[s]; sim[idx] = vi[s];
    }
    __syncthreads();
#pragma unroll
    for (int n2 = 0; n2 < 16; n2++) {
        int idx = (16 * t + n2) * SM_STRIDE + l;
        vr[n2] = sre[idx]; vi[n2] = sim[idx];
    }
    fft16_reg(vr, vi);
    __syncthreads();
#pragma unroll
    for (int s = 0; s < 16; s++) {
        int k2 = 4 * (s & 3) + (s >> 2);
        int idx = (16 * k2 + t) * SM_STRIDE + l;
        sre[idx] = vr[s]; sim[idx] = vi[s];
    }
    __syncthreads();
}

// ---------------------------------------------------------------------------
// Pass 1: FFT along the contiguous input axis; 32 lines of 256 per block.
// MODE 0 (Fx): lines (c,y) over z; in/out row-major   -> g_tmp [c][y][z]
// MODE 1 (Fy): lines (f,x,d) over z; out [z][d]       -> g_tmp [f][x][z][d]
// MODE 2 (Fz): in/out interleaved [y][d] per (f,x)    -> g_tmp [f][x][y][d]
// ---------------------------------------------------------------------------
template<int MODE>
__global__ __launch_bounds__(512) void fft_pass1(const float* __restrict__ in_re,
                                                 const float* __restrict__ in_im) {
    extern __shared__ float smem[];
    float* sre = smem;
    float* sim = smem + SM_ELEMS;
    float* twr = smem + 2 * SM_ELEMS;
    float* twi = twr + 256;
    int tid = threadIdx.x;
    if (tid < 256) { twr[tid] = g_twre[tid]; twi[tid] = g_twim[tid]; }
    float alpha = g_alpha;
    long long base = (long long)blockIdx.x << 13;          // 32 lines * 256
#pragma unroll
    for (int s = 0; s < 16; s++) {
        int idx = tid + (s << 9);
        int m, rl;
        if (MODE == 2) { m = (idx >> 3) & 255; rl = ((idx >> 11) << 3) | (idx & 7); }
        else           { m = idx & 255;        rl = idx >> 8; }
        sre[m * SM_STRIDE + rl] = in_re[base + idx] * alpha;
        sim[m * SM_STRIDE + rl] = in_im[base + idx] * alpha;
    }
    __syncthreads();
    fft256_lines(sre, sim, twr, twi, tid & 31, tid >> 5);
#pragma unroll
    for (int s = 0; s < 16; s++) {
        int idx = tid + (s << 9);
        float vr, vi;
        if (MODE == 0) {
            vr = sre[(idx & 255) * SM_STRIDE + (idx >> 8)];
            vi = sim[(idx & 255) * SM_STRIDE + (idx >> 8)];
        } else {
            int fx8 = (idx >> 11) << 3, m = (idx >> 3) & 255, d = idx & 7;
            vr = sre[m * SM_STRIDE + fx8 + d];
            vi = sim[m * SM_STRIDE + fx8 + d];
        }
        g_tmp_re[base + idx] = vr;
        g_tmp_im[base + idx] = vi;
    }
}

// ---------------------------------------------------------------------------
// Pass 2: FFT along the strided axis of g_tmp + fp16 pack into g_volh.
//  VID 0 (Fx): g_tmp [c][y][z]; block = 4 c x 8 z, FFT over y.
//              texel (h=y, w=z): 4 consecutive c half2 -> one 16B store.
//  VID 1 (Fy): g_tmp [f][x][z][d]; block = 1 f x (4 z x 8 d), FFT over x.
//              texel (h=x, w=z): c=8f+d -> two 16B stores.
//  VID 2 (Fz): g_tmp [f][x][y][d]; same, texel (h=y, w=x).
// ---------------------------------------------------------------------------
template<int VID>
__global__ __launch_bounds__(512) void fft_pass2() {
    extern __shared__ float smem[];
    float* sre = smem;
    float* sim = smem + SM_ELEMS;
    float* twr = smem + 2 * SM_ELEMS;
    float* twi = twr + 256;
    int tid = threadIdx.x;
    if (tid < 256) { twr[tid] = g_twre[tid]; twi[tid] = g_twim[tid]; }
    if (VID == 0) {
        int c0 = blockIdx.y << 2, z0 = blockIdx.x << 3;
#pragma unroll
        for (int s = 0; s < 16; s++) {
            int u = tid + (s << 9);
            int zs = u & 7, cs = (u >> 3) & 3, k = u >> 5;
            int src = (c0 + cs) * 65536 + k * 256 + z0 + zs;
            int rl = (cs << 3) + zs;
            sre[k * SM_STRIDE + rl] = g_tmp_re[src];
            sim[k * SM_STRIDE + rl] = g_tmp_im[src];
        }
    } else {
        int f = blockIdx.y, i0 = blockIdx.x << 5;
#pragma unroll
        for (int s = 0; s < 16; s++) {
            int u = tid + (s << 9);
            int rl = u & 31, k = u >> 5;
            int src = f * 524288 + k * 2048 + i0 + rl;
            sre[k * SM_STRIDE + rl] = g_tmp_re[src];
            sim[k * SM_STRIDE + rl] = g_tmp_im[src];
        }
    }
    __syncthreads();
    fft256_lines(sre, sim, twr, twi, tid & 31, tid >> 5);
    // Store: pack 4 channels (half2 each) into one 16B burst.
    uint4* vol = reinterpret_cast<uint4*>(g_volh[VID]);   // 32 uint4 per texel
    if (VID == 0) {
        int c0 = blockIdx.y << 2, z0 = blockIdx.x << 3;
#pragma unroll
        for (int s = 0; s < 4; s++) {
            int u = tid + (s << 9);
            int zs = u & 7, k = u >> 3;
            int sb = k * SM_STRIDE + zs;
            __half2 h0 = __floats2half2_rn(sre[sb],      sim[sb]);
            __half2 h1 = __floats2half2_rn(sre[sb + 8],  sim[sb + 8]);
            __half2 h2 = __floats2half2_rn(sre[sb + 16], sim[sb + 16]);
            __half2 h3 = __floats2half2_rn(sre[sb + 24], sim[sb + 24]);
            uint4 pk;
            pk.x = *reinterpret_cast<unsigned*>(&h0);
            pk.y = *reinterpret_cast<unsigned*>(&h1);
            pk.z = *reinterpret_cast<unsigned*>(&h2);
            pk.w = *reinterpret_cast<unsigned*>(&h3);
            int texel = (k << 8) + z0 + zs;
            vol[(texel << 5) + (c0 >> 2)] = pk;
        }
    } else {
        int f = blockIdx.y, i0 = blockIdx.x << 5;
        int w0 = i0 >> 3;                      // first z (VID1) or y (VID2)
        // 2048 stores per block: 256 k x 4 zz x 2 j  (R9 bug was s<2 -> half
        // the k range never written; must be s<4)
#pragma unroll
        for (int s = 0; s < 4; s++) {
            int u = tid + (s << 9);
            int j = u & 1, zz = (u >> 1) & 3, k = u >> 3;
            int sb = k * SM_STRIDE + (zz << 3) + (j << 2);
            __half2 h0 = __floats2half2_rn(sre[sb],     sim[sb]);
            __half2 h1 = __floats2half2_rn(sre[sb + 1], sim[sb + 1]);
            __half2 h2 = __floats2half2_rn(sre[sb + 2], sim[sb + 2]);
            __half2 h3 = __floats2half2_rn(sre[sb + 3], sim[sb + 3]);
            uint4 pk;
            pk.x = *reinterpret_cast<unsigned*>(&h0);
            pk.y = *reinterpret_cast<unsigned*>(&h1);
            pk.z = *reinterpret_cast<unsigned*>(&h2);
            pk.w = *reinterpret_cast<unsigned*>(&h3);
            int texel = (VID == 1) ? ((k << 8) + w0 + zz)
                                   : (((w0 + zz) << 8) + k);
            vol[(texel << 5) + (f << 1) + j] = pk;
        }
    }
}

// ---------------------------------------------------------------------------
// Gather: one warp per point. Lane L owns channels c = 4L..4L+3 (f = L/2,
// d = 4*(L&1)+j). Each tap = one LDG.128 (4 channels fp16 complex).
// ---------------------------------------------------------------------------
__device__ __forceinline__ void tap_acc(const uint4* __restrict__ V, int b, float w,
                                        float& rr0, float& ri0, float& rr1, float& ri1,
                                        float& rr2, float& ri2, float& rr3, float& ri3) {
    uint4 a = V[b];
    float2 f0 = __half22float2(*reinterpret_cast<__half2*>(&a.x));
    float2 f1 = __half22float2(*reinterpret_cast<__half2*>(&a.y));
    float2 f2 = __half22float2(*reinterpret_cast<__half2*>(&a.z));
    float2 f3 = __half22float2(*reinterpret_cast<__half2*>(&a.w));
    rr0 += w * f0.x; ri0 += w * f0.y;
    rr1 += w * f1.x; ri1 += w * f1.y;
    rr2 += w * f2.x; ri2 += w * f2.y;
    rr3 += w * f3.x; ri3 += w * f3.y;
}

__global__ __launch_bounds__(256) void gather_kernel(const float* __restrict__ pts,
                                                     float* __restrict__ out) {
    int warp = (blockIdx.x << 3) + (threadIdx.x >> 5);
    int lane = threadIdx.x & 31;

    const float px = pts[warp * 3 + 0];
    const float py = pts[warp * 3 + 1];
    const float pz = pts[warp * 3 + 2];

    float cval, sval;
    {
        int a = lane >> 3, d = lane & 7;
        float q  = (a == 0) ? px : ((a == 1) ? py : pz);
        float xx = (q + 1.0f) * (0.5f * 255.0f / 256.0f);
        float s_, c_;
        sincospif(2.0f * xx * (float)d, &s_, &c_);
        float sc = d ? 2.0f : 1.0f;
        cval = c_ * sc;
        sval = s_ * sc;
    }

    int q0[3], q1[3]; float wf[3];
    {
        float qv[3] = { px, py, pz };
#pragma unroll
        for (int a = 0; a < 3; a++) {
            float ii = (qv[a] + 1.0f) * 127.5f;
            float f0 = floorf(ii);
            wf[a] = ii - f0;
            int i0 = (int)f0;
            i0 = max(0, min(255, i0));
            q0[a] = i0;
            q1[a] = min(i0 + 1, 255);
        }
    }

    float acc = 0.0f;
    int dhalf = (lane & 1) << 2;
#pragma unroll
    for (int v = 0; v < 3; v++) {
        int h0, h1, w0, w1; float wy, wx;
        if (v == 0)      { h0 = q0[1]; h1 = q1[1]; wy = wf[1]; w0 = q0[2]; w1 = q1[2]; wx = wf[2]; }
        else if (v == 1) { h0 = q0[0]; h1 = q1[0]; wy = wf[0]; w0 = q0[2]; w1 = q1[2]; wx = wf[2]; }
        else             { h0 = q0[1]; h1 = q1[1]; wy = wf[1]; w0 = q0[0]; w1 = q1[0]; wx = wf[0]; }
        float w00 = (1.0f - wy) * (1.0f - wx);
        float w01 = (1.0f - wy) * wx;
        float w10 = wy * (1.0f - wx);
        float w11 = wy * wx;

        const uint4* V = reinterpret_cast<const uint4*>(g_volh[v]);
        int b00 = (((h0 << 8) + w0) << 5) + lane;
        int b01 = (((h0 << 8) + w1) << 5) + lane;
        int b10 = (((h1 << 8) + w0) << 5) + lane;
        int b11 = (((h1 << 8) + w1) << 5) + lane;

        float rr0 = 0, ri0 = 0, rr1 = 0, ri1 = 0, rr2 = 0, ri2 = 0, rr3 = 0, ri3 = 0;
        tap_acc(V, b00, w00, rr0, ri0, rr1, ri1, rr2, ri2, rr3, ri3);
        tap_acc(V, b01, w01, rr0, ri0, rr1, ri1, rr2, ri2, rr3, ri3);
        tap_acc(V, b10, w10, rr0, ri0, rr1, ri1, rr2, ri2, rr3, ri3);
        tap_acc(V, b11, w11, rr0, ri0, rr1, ri1, rr2, ri2, rr3, ri3);

        int sb = (v << 3) + dhalf;
        float tc0 = __shfl_sync(0xffffffffu, cval, sb + 0);
        float ts0 = __shfl_sync(0xffffffffu, sval, sb + 0);
        float tc1 = __shfl_sync(0xffffffffu, cval, sb + 1);
        float ts1 = __shfl_sync(0xffffffffu, sval, sb + 1);
        float tc2 = __shfl_sync(0xffffffffu, cval, sb + 2);
        float ts2 = __shfl_sync(0xffffffffu, sval, sb + 2);
        float tc3 = __shfl_sync(0xffffffffu, cval, sb + 3);
        float ts3 = __shfl_sync(0xffffffffu, sval, sb + 3);

        acc += rr0 * tc0 - ri0 * ts0;
        acc += rr1 * tc1 - ri1 * ts1;
        acc += rr2 * tc2 - ri2 * ts2;
        acc += rr3 * tc3 - ri3 * ts3;
    }

    acc += __shfl_xor_sync(0xffffffffu, acc, 1);
    if ((lane & 1) == 0) out[(warp << 4) + (lane >> 1)] = acc;
}

// ---------------------------------------------------------------------------
extern "C" void kernel_launch(void* const* d_in, const int* in_sizes, int n_in,
                              void* d_out, int out_size) {
    const float* pts   = (const float*)d_in[0];
    const float* Fx_re = (const float*)d_in[1];
    const float* Fx_im = (const float*)d_in[2];
    const float* Fy_re = (const float*)d_in[3];
    const float* Fy_im = (const float*)d_in[4];
    const float* Fz_re = (const float*)d_in[5];
    const float* Fz_im = (const float*)d_in[6];
    const float* ap    = (const float*)d_in[7];
    float* out = (float*)d_out;

    cudaFuncSetAttribute(fft_pass1<0>, cudaFuncAttributeMaxDynamicSharedMemorySize, SM_BYTES);
    cudaFuncSetAttribute(fft_pass1<1>, cudaFuncAttributeMaxDynamicSharedMemorySize, SM_BYTES);
    cudaFuncSetAttribute(fft_pass1<2>, cudaFuncAttributeMaxDynamicSharedMemorySize, SM_BYTES);
    cudaFuncSetAttribute(fft_pass2<0>, cudaFuncAttributeMaxDynamicSharedMemorySize, SM_BYTES);
    cudaFuncSetAttribute(fft_pass2<1>, cudaFuncAttributeMaxDynamicSharedMemorySize, SM_BYTES);
    cudaFuncSetAttribute(fft_pass2<2>, cudaFuncAttributeMaxDynamicSharedMemorySize, SM_BYTES);

    init_kernel<<<1, 256>>>(ap);

    // Fx: [c=128][y][z]; pass1 along z, pass2 along y
    fft_pass1<0><<<1024, 512, SM_BYTES>>>(Fx_re, Fx_im);
    fft_pass2<0><<<dim3(32, 32), 512, SM_BYTES>>>();

    // Fy: [f][x][d][z]; pass1 along z (out [z][d]), pass2 along x
    fft_pass1<1><<<1024, 512, SM_BYTES>>>(Fy_re, Fy_im);
    fft_pass2<1><<<dim3(64, 16), 512, SM_BYTES>>>();

    // Fz: [f][x][y][d]; pass1 along y (out [y][d]), pass2 along x
    fft_pass1<2><<<1024, 512, SM_BYTES>>>(Fz_re, Fz_im);
    fft_pass2<2><<<dim3(64, 16), 512, SM_BYTES>>>();

    gather_kernel<<<16384, 256>>>(pts, out);
}

// round 15
// speedup vs baseline: 2.8091x; 1.0944x over previous
#include <cuda_runtime.h>
#include <cuda_fp16.h>

// ---------------------------------------------------------------------------
//   volumes: 3 × [128 complex channels][256][256];  points: 131072 -> [N][16]
//   FFT: four-step 256 = 16 x 16, register FFT16s, conflict-free smem.
//   R15: three pass1 launches merged into one (3072 blocks), same for pass2.
//   Sample volumes fp16 (half2 re,im): 3 x 32 MB -> L2-resident for gather.
// ---------------------------------------------------------------------------

__device__ float g_alpha;
__device__ float g_twre[256];              // W256^j = exp(+2*pi*i*j/256)
__device__ float g_twim[256];
__device__ float g_tmp_re[3][8388608];     // 3 x 32 MB (per-volume pass-1 out)
__device__ float g_tmp_im[3][8388608];
// Final sample volumes, fp16 interleaved: [H=256][W=256][C=128] half2(re,im)
__device__ __half2 g_volh[3][8388608];     // 3 × 32 MB

// smem layout (dynamic): sre[8448] | sim[8448] | twr[256] | twi[256]
#define SM_STRIDE 33
#define SM_ELEMS  8448
#define SM_FLOATS (2 * SM_ELEMS + 512)
#define SM_BYTES  (SM_FLOATS * 4)

// ---------------------------------------------------------------------------
__global__ void init_kernel(const float* __restrict__ alpha_params) {
    int t = threadIdx.x;
    if (t < 256) {
        float s, c;
        sincospif((float)t * (1.0f / 128.0f), &s, &c);   // 2*pi*t/256
        g_twre[t] = c;
        g_twim[t] = s;
    }
    if (t == 0) {
        float a  = alpha_params[0];
        float bx = 10.0f * a;
        g_alpha = (bx > 1.0f) ? a : 0.1f * log1pf(expf(fminf(bx, 30.0f)));
    }
}

// ---------------------------------------------------------------------------
// 16-point inverse DFT (sign +, unnormalized), DIF radix-4, in registers.
// Natural-order input; output X16[4q+r] lands in slot [4r+q].
// ---------------------------------------------------------------------------
#define C1_ 0.92387953251128675613f
#define S1_ 0.38268343236508977173f
#define R2_ 0.70710678118654752440f

__device__ __forceinline__ void fft16_reg(float* vr, float* vi) {
#pragma unroll
    for (int m = 0; m < 4; m++) {
        float t0r = vr[m]   + vr[m+8],  t0i = vi[m]   + vi[m+8];
        float t2r = vr[m]   - vr[m+8],  t2i = vi[m]   - vi[m+8];
        float t1r = vr[m+4] + vr[m+12], t1i = vi[m+4] + vi[m+12];
        float t3r = vr[m+4] - vr[m+12], t3i = vi[m+4] - vi[m+12];
        vr[m]    = t0r + t1r;  vi[m]    = t0i + t1i;
        vr[m+4]  = t2r - t3i;  vi[m+4]  = t2i + t3r;   // t2 + i*t3
        vr[m+8]  = t0r - t1r;  vi[m+8]  = t0i - t1i;
        vr[m+12] = t2r + t3i;  vi[m+12] = t2i - t3r;   // t2 - i*t3
    }
    const float TWR[16] = {1,1,1,1,  1,C1_,R2_,S1_,  1,R2_,0.f,-R2_,  1,S1_,-R2_,-C1_};
    const float TWI[16] = {0,0,0,0,  0,S1_,R2_,C1_,  0,R2_,1.f, R2_,  0,C1_, R2_,-S1_};
#pragma unroll
    for (int s = 5; s < 16; s++) {
        if ((s & 3) == 0) continue;   // pos = 0 -> twiddle 1
        float wr = TWR[s], wi = TWI[s];
        float xr = vr[s], xi = vi[s];
        vr[s] = xr * wr - xi * wi;
        vi[s] = xr * wi + xi * wr;
    }
#pragma unroll
    for (int r = 0; r < 4; r++) {
        int b = 4 * r;
        float t0r = vr[b]   + vr[b+2], t0i = vi[b]   + vi[b+2];
        float t2r = vr[b]   - vr[b+2], t2i = vi[b]   - vi[b+2];
        float t1r = vr[b+1] + vr[b+3], t1i = vi[b+1] + vi[b+3];
        float t3r = vr[b+1] - vr[b+3], t3i = vi[b+1] - vi[b+3];
        vr[b]   = t0r + t1r; vi[b]   = t0i + t1i;
        vr[b+1] = t2r - t3i; vi[b+1] = t2i + t3r;
        vr[b+2] = t0r - t1r; vi[b+2] = t0i - t1i;
        vr[b+3] = t2r + t3i; vi[b+3] = t2i - t3r;
    }
}

// ---------------------------------------------------------------------------
// Four-step 256-pt inverse FFT on 32 lines held in smem (element m of line l
// at sre/sim[m*33 + l]). t = tid>>5 (warp id), l = lane. Conflict-free.
// ---------------------------------------------------------------------------
__device__ __forceinline__ void fft256_lines(float* sre, float* sim,
                                             const float* twr, const float* twi,
                                             int l, int t) {
    float vr[16], vi[16];
#pragma unroll
    for (int n1 = 0; n1 < 16; n1++) {
        int idx = (16 * n1 + t) * SM_STRIDE + l;
        vr[n1] = sre[idx]; vi[n1] = sim[idx];
    }
    fft16_reg(vr, vi);
#pragma unroll
    for (int s = 0; s < 16; s++) {
        int k1 = 4 * (s & 3) + (s >> 2);
        int e = (t * k1) & 255;
        float wr = twr[e], wi = twi[e];      // warp-uniform -> broadcast
        float xr = vr[s], xi = vi[s];
        vr[s] = xr * wr - xi * wi;
        vi[s] = xr * wi + xi * wr;
    }
    __syncthreads();
#pragma unroll
    for (int s = 0; s < 16; s++) {
        int k1 = 4 * (s & 3) + (s >> 2);
        int idx = (16 * k1 + t) * SM_STRIDE + l;
        sre[idx] = vr[s]; sim[idx] = vi[s];
    }
    __syncthreads();
#pragma unroll
    for (int n2 = 0; n2 < 16; n2++) {
        int idx = (16 * t + n2) * SM_STRIDE + l;
        vr[n2] = sre[idx]; vi[n2] = sim[idx];
    }
    fft16_reg(vr, vi);
    __syncthreads();
#pragma unroll
    for (int s = 0; s < 16; s++) {
        int k2 = 4 * (s & 3) + (s >> 2);
        int idx = (16 * k2 + t) * SM_STRIDE + l;
        sre[idx] = vr[s]; sim[idx] = vi[s];
    }
    __syncthreads();
}

// ---------------------------------------------------------------------------
// Pass 1 (all volumes, 3072 blocks): vid = blockIdx.x >> 10, bid = low bits.
// vid 0 (Fx): lines (c,y) over z; in/out row-major   -> tmp[0] [c][y][z]
// vid 1 (Fy): lines (f,x,d) over z; out [z][d]       -> tmp[1] [f][x][z][d]
// vid 2 (Fz): in interleaved [y][d]; out [y][d]      -> tmp[2] [f][x][y][d]
// ---------------------------------------------------------------------------
__global__ __launch_bounds__(512) void fft_pass1_all(
    const float* __restrict__ xre, const float* __restrict__ xim,
    const float* __restrict__ yre, const float* __restrict__ yim,
    const float* __restrict__ zre, const float* __restrict__ zim) {
    extern __shared__ float smem[];
    float* sre = smem;
    float* sim = smem + SM_ELEMS;
    float* twr = smem + 2 * SM_ELEMS;
    float* twi = twr + 256;
    int tid = threadIdx.x;
    if (tid < 256) { twr[tid] = g_twre[tid]; twi[tid] = g_twim[tid]; }
    int vid = blockIdx.x >> 10;
    int bid = blockIdx.x & 1023;
    const float* in_re = (vid == 0) ? xre : ((vid == 1) ? yre : zre);
    const float* in_im = (vid == 0) ? xim : ((vid == 1) ? yim : zim);
    float* tre = g_tmp_re[vid];
    float* tim = g_tmp_im[vid];
    float alpha = g_alpha;
    int base = bid << 13;                                  // 32 lines * 256
#pragma unroll
    for (int s = 0; s < 16; s++) {
        int idx = tid + (s << 9);
        int m, rl;
        if (vid == 2) { m = (idx >> 3) & 255; rl = ((idx >> 11) << 3) | (idx & 7); }
        else          { m = idx & 255;        rl = idx >> 8; }
        sre[m * SM_STRIDE + rl] = in_re[base + idx] * alpha;
        sim[m * SM_STRIDE + rl] = in_im[base + idx] * alpha;
    }
    __syncthreads();
    fft256_lines(sre, sim, twr, twi, tid & 31, tid >> 5);
#pragma unroll
    for (int s = 0; s < 16; s++) {
        int idx = tid + (s << 9);
        float vr, vi;
        if (vid == 0) {
            vr = sre[(idx & 255) * SM_STRIDE + (idx >> 8)];
            vi = sim[(idx & 255) * SM_STRIDE + (idx >> 8)];
        } else {
            int fx8 = (idx >> 11) << 3, m = (idx >> 3) & 255, d = idx & 7;
            vr = sre[m * SM_STRIDE + fx8 + d];
            vi = sim[m * SM_STRIDE + fx8 + d];
        }
        tre[base + idx] = vr;
        tim[base + idx] = vi;
    }
}

// ---------------------------------------------------------------------------
// Pass 2 (all volumes, 3072 blocks): FFT along strided axis + fp16 pack.
// vid 0 (Fx): tmp[0] [c][y][z]; block = 4 c x 8 z (bid: y=c-grp<<5|z-grp).
//             texel (h=y, w=z): 4 consecutive c half2 -> one 16B store.
// vid 1 (Fy): tmp[1] [f][x][z][d]; block = 1 f x 32 i (bid: f<<6|i-grp).
//             texel (h=x, w=z): c=8f+d -> two 16B stores.
// vid 2 (Fz): tmp[2] [f][x][y][d]; same, texel (h=y, w=x).
// ---------------------------------------------------------------------------
__global__ __launch_bounds__(512) void fft_pass2_all() {
    extern __shared__ float smem[];
    float* sre = smem;
    float* sim = smem + SM_ELEMS;
    float* twr = smem + 2 * SM_ELEMS;
    float* twi = twr + 256;
    int tid = threadIdx.x;
    if (tid < 256) { twr[tid] = g_twre[tid]; twi[tid] = g_twim[tid]; }
    int vid = blockIdx.x >> 10;
    int bid = blockIdx.x & 1023;
    const float* tre = g_tmp_re[vid];
    const float* tim = g_tmp_im[vid];
    if (vid == 0) {
        int c0 = (bid >> 5) << 2, z0 = (bid & 31) << 3;
#pragma unroll
        for (int s = 0; s < 16; s++) {
            int u = tid + (s << 9);
            int zs = u & 7, cs = (u >> 3) & 3, k = u >> 5;
            int src = (c0 + cs) * 65536 + k * 256 + z0 + zs;
            int rl = (cs << 3) + zs;
            sre[k * SM_STRIDE + rl] = tre[src];
            sim[k * SM_STRIDE + rl] = tim[src];
        }
    } else {
        int f = bid >> 6, i0 = (bid & 63) << 5;
#pragma unroll
        for (int s = 0; s < 16; s++) {
            int u = tid + (s << 9);
            int rl = u & 31, k = u >> 5;
            int src = f * 524288 + k * 2048 + i0 + rl;
            sre[k * SM_STRIDE + rl] = tre[src];
            sim[k * SM_STRIDE + rl] = tim[src];
        }
    }
    __syncthreads();
    fft256_lines(sre, sim, twr, twi, tid & 31, tid >> 5);
    // Store: pack 4 channels (half2 each) into one 16B burst.
    uint4* vol = reinterpret_cast<uint4*>(g_volh[vid]);   // 32 uint4 per texel
    if (vid == 0) {
        int c0 = (bid >> 5) << 2, z0 = (bid & 31) << 3;
#pragma unroll
        for (int s = 0; s < 4; s++) {
            int u = tid + (s << 9);
            int zs = u & 7, k = u >> 3;
            int sb = k * SM_STRIDE + zs;
            __half2 h0 = __floats2half2_rn(sre[sb],      sim[sb]);
            __half2 h1 = __floats2half2_rn(sre[sb + 8],  sim[sb + 8]);
            __half2 h2 = __floats2half2_rn(sre[sb + 16], sim[sb + 16]);
            __half2 h3 = __floats2half2_rn(sre[sb + 24], sim[sb + 24]);
            uint4 pk;
            pk.x = *reinterpret_cast<unsigned*>(&h0);
            pk.y = *reinterpret_cast<unsigned*>(&h1);
            pk.z = *reinterpret_cast<unsigned*>(&h2);
            pk.w = *reinterpret_cast<unsigned*>(&h3);
            int texel = (k << 8) + z0 + zs;
            vol[(texel << 5) + (c0 >> 2)] = pk;
        }
    } else {
        int f = bid >> 6, i0 = (bid & 63) << 5;
        int w0 = i0 >> 3;                      // first z (vid1) or y (vid2)
        // 2048 stores per block: 256 k x 4 zz x 2 j
#pragma unroll
        for (int s = 0; s < 4; s++) {
            int u = tid + (s << 9);
            int j = u & 1, zz = (u >> 1) & 3, k = u >> 3;
            int sb = k * SM_STRIDE + (zz << 3) + (j << 2);
            __half2 h0 = __floats2half2_rn(sre[sb],     sim[sb]);
            __half2 h1 = __floats2half2_rn(sre[sb + 1], sim[sb + 1]);
            __half2 h2 = __floats2half2_rn(sre[sb + 2], sim[sb + 2]);
            __half2 h3 = __floats2half2_rn(sre[sb + 3], sim[sb + 3]);
            uint4 pk;
            pk.x = *reinterpret_cast<unsigned*>(&h0);
            pk.y = *reinterpret_cast<unsigned*>(&h1);
            pk.z = *reinterpret_cast<unsigned*>(&h2);
            pk.w = *reinterpret_cast<unsigned*>(&h3);
            int texel = (vid == 1) ? ((k << 8) + w0 + zz)
                                   : (((w0 + zz) << 8) + k);
            vol[(texel << 5) + (f << 1) + j] = pk;
        }
    }
}

// ---------------------------------------------------------------------------
// Gather: one warp per point. Lane L owns channels c = 4L..4L+3 (f = L/2,
// d = 4*(L&1)+j). Each tap = one LDG.128 (4 channels fp16 complex).
// ---------------------------------------------------------------------------
__device__ __forceinline__ void tap_acc(const uint4* __restrict__ V, int b, float w,
                                        float& rr0, float& ri0, float& rr1, float& ri1,
                                        float& rr2, float& ri2, float& rr3, float& ri3) {
    uint4 a = V[b];
    float2 f0 = __half22float2(*reinterpret_cast<__half2*>(&a.x));
    float2 f1 = __half22float2(*reinterpret_cast<__half2*>(&a.y));
    float2 f2 = __half22float2(*reinterpret_cast<__half2*>(&a.z));
    float2 f3 = __half22float2(*reinterpret_cast<__half2*>(&a.w));
    rr0 += w * f0.x; ri0 += w * f0.y;
    rr1 += w * f1.x; ri1 += w * f1.y;
    rr2 += w * f2.x; ri2 += w * f2.y;
    rr3 += w * f3.x; ri3 += w * f3.y;
}

__global__ __launch_bounds__(256) void gather_kernel(const float* __restrict__ pts,
                                                     float* __restrict__ out) {
    int warp = (blockIdx.x << 3) + (threadIdx.x >> 5);
    int lane = threadIdx.x & 31;

    const float px = pts[warp * 3 + 0];
    const float py = pts[warp * 3 + 1];
    const float pz = pts[warp * 3 + 2];

    float cval, sval;
    {
        int a = lane >> 3, d = lane & 7;
        float q  = (a == 0) ? px : ((a == 1) ? py : pz);
        float xx = (q + 1.0f) * (0.5f * 255.0f / 256.0f);
        float s_, c_;
        sincospif(2.0f * xx * (float)d, &s_, &c_);
        float sc = d ? 2.0f : 1.0f;
        cval = c_ * sc;
        sval = s_ * sc;
    }

    int q0[3], q1[3]; float wf[3];
    {
        float qv[3] = { px, py, pz };
#pragma unroll
        for (int a = 0; a < 3; a++) {
            float ii = (qv[a] + 1.0f) * 127.5f;
            float f0 = floorf(ii);
            wf[a] = ii - f0;
            int i0 = (int)f0;
            i0 = max(0, min(255, i0));
            q0[a] = i0;
            q1[a] = min(i0 + 1, 255);
        }
    }

    float acc = 0.0f;
    int dhalf = (lane & 1) << 2;
#pragma unroll
    for (int v = 0; v < 3; v++) {
        int h0, h1, w0, w1; float wy, wx;
        if (v == 0)      { h0 = q0[1]; h1 = q1[1]; wy = wf[1]; w0 = q0[2]; w1 = q1[2]; wx = wf[2]; }
        else if (v == 1) { h0 = q0[0]; h1 = q1[0]; wy = wf[0]; w0 = q0[2]; w1 = q1[2]; wx = wf[2]; }
        else             { h0 = q0[1]; h1 = q1[1]; wy = wf[1]; w0 = q0[0]; w1 = q1[0]; wx = wf[0]; }
        float w00 = (1.0f - wy) * (1.0f - wx);
        float w01 = (1.0f - wy) * wx;
        float w10 = wy * (1.0f - wx);
        float w11 = wy * wx;

        const uint4* V = reinterpret_cast<const uint4*>(g_volh[v]);
        int b00 = (((h0 << 8) + w0) << 5) + lane;
        int b01 = (((h0 << 8) + w1) << 5) + lane;
        int b10 = (((h1 << 8) + w0) << 5) + lane;
        int b11 = (((h1 << 8) + w1) << 5) + lane;

        float rr0 = 0, ri0 = 0, rr1 = 0, ri1 = 0, rr2 = 0, ri2 = 0, rr3 = 0, ri3 = 0;
        tap_acc(V, b00, w00, rr0, ri0, rr1, ri1, rr2, ri2, rr3, ri3);
        tap_acc(V, b01, w01, rr0, ri0, rr1, ri1, rr2, ri2, rr3, ri3);
        tap_acc(V, b10, w10, rr0, ri0, rr1, ri1, rr2, ri2, rr3, ri3);
        tap_acc(V, b11, w11, rr0, ri0, rr1, ri1, rr2, ri2, rr3, ri3);

        int sb = (v << 3) + dhalf;
        float tc0 = __shfl_sync(0xffffffffu, cval, sb + 0);
        float ts0 = __shfl_sync(0xffffffffu, sval, sb + 0);
        float tc1 = __shfl_sync(0xffffffffu, cval, sb + 1);
        float ts1 = __shfl_sync(0xffffffffu, sval, sb + 1);
        float tc2 = __shfl_sync(0xffffffffu, cval, sb + 2);
        float ts2 = __shfl_sync(0xffffffffu, sval, sb + 2);
        float tc3 = __shfl_sync(0xffffffffu, cval, sb + 3);
        float ts3 = __shfl_sync(0xffffffffu, sval, sb + 3);

        acc += rr0 * tc0 - ri0 * ts0;
        acc += rr1 * tc1 - ri1 * ts1;
        acc += rr2 * tc2 - ri2 * ts2;
        acc += rr3 * tc3 - ri3 * ts3;
    }

    acc += __shfl_xor_sync(0xffffffffu, acc, 1);
    if ((lane & 1) == 0) out[(warp << 4) + (lane >> 1)] = acc;
}

// ---------------------------------------------------------------------------
extern "C" void kernel_launch(void* const* d_in, const int* in_sizes, int n_in,
                              void* d_out, int out_size) {
    const float* pts   = (const float*)d_in[0];
    const float* Fx_re = (const float*)d_in[1];
    const float* Fx_im = (const float*)d_in[2];
    const float* Fy_re = (const float*)d_in[3];
    const float* Fy_im = (const float*)d_in[4];
    const float* Fz_re = (const float*)d_in[5];
    const float* Fz_im = (const float*)d_in[6];
    const float* ap    = (const float*)d_in[7];
    float* out = (float*)d_out;

    cudaFuncSetAttribute(fft_pass1_all, cudaFuncAttributeMaxDynamicSharedMemorySize, SM_BYTES);
    cudaFuncSetAttribute(fft_pass2_all, cudaFuncAttributeMaxDynamicSharedMemorySize, SM_BYTES);

    init_kernel<<<1, 256>>>(ap);
    fft_pass1_all<<<3072, 512, SM_BYTES>>>(Fx_re, Fx_im, Fy_re, Fy_im, Fz_re, Fz_im);
    fft_pass2_all<<<3072, 512, SM_BYTES>>>();
    gather_kernel<<<16384, 256>>>(pts, out);
}